// round 2
// baseline (speedup 1.0000x reference)
#include <cuda_runtime.h>

#define N_ROWS 8192
#define F_DIM  512
#define H1_DIM 512
#define SU_DIM 256
#define T_STEPS 16
#define BETA_F 0.95f
#define THR_F  1.0f

// ---------------- scratch (static device globals; no allocations) ----------------
__device__ float    g_cur0[N_ROWS * H1_DIM];                   // 16 MB
__device__ unsigned g_spk1[N_ROWS * T_STEPS * (H1_DIM / 32)];  // 8 MB  [n][t][w]
__device__ float    g_sf[N_ROWS * SU_DIM];                     // 8 MB
__device__ float    g_W2T[H1_DIM * SU_DIM];                    // [j][i]
__device__ float    g_WeffT[SU_DIM * F_DIM];                   // [i][f]
__device__ float    g_beff[F_DIM];

// packed fp32x2 add (Blackwell)
__device__ __forceinline__ unsigned long long addx2(unsigned long long a,
                                                    unsigned long long b) {
    unsigned long long r;
    asm("add.rn.f32x2 %0, %1, %2;" : "=l"(r) : "l"(a), "l"(b));
    return r;
}

// ---------------- small prep kernels ----------------
__global__ __launch_bounds__(256) void k_w2t(const float* __restrict__ W2) {
    int idx = blockIdx.x * 256 + threadIdx.x;   // idx < 256*512
    int i = idx >> 9;
    int j = idx & 511;
    g_W2T[j * SU_DIM + i] = W2[idx];
}

// WeffT[i][f] = sum_l Wfu[f][l] * Wf[l][i] + Wfu[f][256+i]
__global__ __launch_bounds__(256) void k_wefft(const float* __restrict__ Wfu,
                                               const float* __restrict__ Wf) {
    __shared__ float wrow[256];
    int f = blockIdx.x;          // 0..511
    int i = threadIdx.x;         // 0..255
    wrow[i] = Wfu[f * 512 + i];
    __syncthreads();
    float acc = Wfu[f * 512 + 256 + i];
#pragma unroll 4
    for (int l = 0; l < 256; l++)
        acc = fmaf(wrow[l], Wf[l * 256 + i], acc);
    g_WeffT[i * 512 + f] = acc;
}

// beff[f] = sum_l Wfu[f][l]*bf[l] + bfu[f]
__global__ __launch_bounds__(512) void k_beff(const float* __restrict__ Wfu,
                                              const float* __restrict__ bf,
                                              const float* __restrict__ bfu) {
    int f = threadIdx.x;  // 512 threads, 1 block
    float acc = bfu[f];
#pragma unroll 4
    for (int l = 0; l < 256; l++)
        acc = fmaf(Wfu[f * 512 + l], bf[l], acc);
    g_beff[f] = acc;
}

// ---------------- K1: cur0 = X @ W1^T + b1  (fp32 tiled GEMM, NT form) ----------------
#define K1_BM 128
#define K1_BN 128
#define K1_BK 16
#define K1_LDS 136

__global__ __launch_bounds__(256) void k_gemm1(const float* __restrict__ X,
                                               const float* __restrict__ W1,
                                               const float* __restrict__ b1) {
    __shared__ float As[K1_BK][K1_LDS];
    __shared__ float Bs[K1_BK][K1_LDS];

    const int n0 = blockIdx.y * K1_BM;
    const int h0 = blockIdx.x * K1_BN;
    const int tid = threadIdx.x;
    const int ty = tid >> 4;        // 0..15 -> row group
    const int tx = tid & 15;        // 0..15 -> col group

    float acc[8][8];
#pragma unroll
    for (int i = 0; i < 8; i++)
#pragma unroll
        for (int j = 0; j < 8; j++) acc[i][j] = 0.f;

    for (int k0 = 0; k0 < 512; k0 += K1_BK) {
#pragma unroll
        for (int p = 0; p < 2; p++) {
            int q = tid + p * 256;          // float4 tile index (512 total per operand)
            int row = q >> 2;
            int kq = q & 3;
            float4 av = *(const float4*)(X + (size_t)(n0 + row) * 512 + k0 + kq * 4);
            As[kq * 4 + 0][row] = av.x;
            As[kq * 4 + 1][row] = av.y;
            As[kq * 4 + 2][row] = av.z;
            As[kq * 4 + 3][row] = av.w;
            float4 bv = *(const float4*)(W1 + (size_t)(h0 + row) * 512 + k0 + kq * 4);
            Bs[kq * 4 + 0][row] = bv.x;
            Bs[kq * 4 + 1][row] = bv.y;
            Bs[kq * 4 + 2][row] = bv.z;
            Bs[kq * 4 + 3][row] = bv.w;
        }
        __syncthreads();
#pragma unroll
        for (int k = 0; k < K1_BK; k++) {
            float a[8], b[8];
            *(float4*)(a)     = *(const float4*)&As[k][ty * 8];
            *(float4*)(a + 4) = *(const float4*)&As[k][ty * 8 + 4];
            *(float4*)(b)     = *(const float4*)&Bs[k][tx * 8];
            *(float4*)(b + 4) = *(const float4*)&Bs[k][tx * 8 + 4];
#pragma unroll
            for (int i = 0; i < 8; i++)
#pragma unroll
                for (int j = 0; j < 8; j++)
                    acc[i][j] = fmaf(a[i], b[j], acc[i][j]);
        }
        __syncthreads();
    }

    float bv[8];
#pragma unroll
    for (int j = 0; j < 8; j++) bv[j] = b1[h0 + tx * 8 + j];

#pragma unroll
    for (int i = 0; i < 8; i++) {
        float4 o0, o1;
        o0.x = acc[i][0] + bv[0]; o0.y = acc[i][1] + bv[1];
        o0.z = acc[i][2] + bv[2]; o0.w = acc[i][3] + bv[3];
        o1.x = acc[i][4] + bv[4]; o1.y = acc[i][5] + bv[5];
        o1.z = acc[i][6] + bv[6]; o1.w = acc[i][7] + bv[7];
        size_t base = (size_t)(n0 + ty * 8 + i) * 512 + h0 + tx * 8;
        *(float4*)(g_cur0 + base)     = o0;
        *(float4*)(g_cur0 + base + 4) = o1;
    }
}

// ---------------- K2: precompute spk1 bitmasks for all 16 steps ----------------
__global__ __launch_bounds__(256) void k_spk1(const float* __restrict__ b1) {
    int idx = blockIdx.x * 256 + threadIdx.x;   // n*512 + j
    int n = idx >> 9;
    int j = idx & 511;
    int lane = threadIdx.x & 31;

    float c0 = g_cur0[idx];
    float bj = b1[j];
    float mem = 0.f;
    float spk = 0.f;
    unsigned myword = 0;
#pragma unroll
    for (int t = 0; t < T_STEPS; t++) {
        float cur = (t == 0) ? c0 : bj;
        mem = fmaf(BETA_F, mem, cur) - spk;
        bool s = (mem - THR_F) > 0.f;
        spk = s ? THR_F : 0.f;
        unsigned w = __ballot_sync(0xffffffffu, s);
        if (lane == t) myword = w;
    }
    if (lane < 16) {
        int w = j >> 5;   // warp-uniform word index 0..15
        g_spk1[((size_t)n * 16 + lane) * 16 + w] = myword;
    }
}

// ---------------- K3: sparse spike-driven layer-2 loop -> spike_features ----------------
// One warp per block. Block covers 64 output columns (i0..i0+63, float2/thread)
// and 16 token rows. Per-block W2T working set = 512 x 64 x 4B = 128 KB -> L1-resident.
// Grid ordered so same-column-chunk blocks co-reside on an SM for whole waves.
__global__ __launch_bounds__(32) void k_spike2(const float* __restrict__ b2) {
    __shared__ unsigned masks[16][16];   // [row][word]
    const int lane = threadIdx.x;
    const int n0 = blockIdx.x * 16;
    const int i0 = blockIdx.y * 64 + lane * 2;

    const unsigned long long b2v = *(const unsigned long long*)(b2 + i0);

    float m2x[16], m2y[16], cntx[16], cnty[16];
#pragma unroll
    for (int r = 0; r < 16; r++) { m2x[r] = m2y[r] = cntx[r] = cnty[r] = 0.f; }
    unsigned spx = 0, spy = 0;   // per-column previous-spike bitfields over rows

    for (int t = 0; t < T_STEPS; t++) {
        __syncwarp();
#pragma unroll
        for (int p = 0; p < 8; p++) {
            int e = lane * 8 + p;          // 0..255
            int r = e >> 4, w = e & 15;
            masks[r][w] = g_spk1[((size_t)(n0 + r) * 16 + t) * 16 + w];
        }
        __syncwarp();

#pragma unroll
        for (int r = 0; r < 16; r++) {
            unsigned long long cur = b2v;
#pragma unroll 1
            for (int w = 0; w < 16; w++) {
                unsigned m = masks[r][w];          // warp-uniform -> convergent loop
                while (m) {
                    int b = __ffs(m) - 1;
                    m &= m - 1;
                    unsigned long long wv =
                        *(const unsigned long long*)(g_W2T + (size_t)(w * 32 + b) * SU_DIM + i0);
                    cur = addx2(cur, wv);
                }
            }
            float cx = __uint_as_float((unsigned)cur);
            float cy = __uint_as_float((unsigned)(cur >> 32));
            float mx = fmaf(BETA_F, m2x[r], cx) - (((spx >> r) & 1u) ? THR_F : 0.f);
            float my = fmaf(BETA_F, m2y[r], cy) - (((spy >> r) & 1u) ? THR_F : 0.f);
            m2x[r] = mx; m2y[r] = my;
            bool sx = (mx - THR_F) > 0.f;
            bool sy = (my - THR_F) > 0.f;
            spx = (spx & ~(1u << r)) | ((unsigned)sx << r);
            spy = (spy & ~(1u << r)) | ((unsigned)sy << r);
            cntx[r] += sx ? 1.f : 0.f;
            cnty[r] += sy ? 1.f : 0.f;
        }
    }

#pragma unroll
    for (int r = 0; r < 16; r++) {
        float2 o;
        o.x = cntx[r] * (1.f / 16.f);
        o.y = cnty[r] * (1.f / 16.f);
        *(float2*)(g_sf + (size_t)(n0 + r) * SU_DIM + i0) = o;
    }
}

// ---------------- K4: y = sf @ Weff^T + beff, LayerNorm, ReLU ----------------
// Block: 256 threads = 8 warps; 32 rows per block; warp owns 4 rows x full 512 cols.
__global__ __launch_bounds__(256) void k_final(const float* __restrict__ ln_g,
                                               const float* __restrict__ ln_b,
                                               float* __restrict__ out) {
    __shared__ float Wc[16][512];    // 32 KB   chunk of WeffT
    __shared__ float sfc[32][16];    // 2 KB

    const int tid = threadIdx.x;
    const int warp = tid >> 5;
    const int lane = tid & 31;
    const int n0 = blockIdx.x * 32;

    float acc[4][16];
#pragma unroll
    for (int r = 0; r < 4; r++)
#pragma unroll
        for (int kk = 0; kk < 16; kk++) acc[r][kk] = 0.f;

    for (int ic = 0; ic < 256; ic += 16) {
        __syncthreads();
#pragma unroll
        for (int p = 0; p < 8; p++) {
            int e4 = tid + p * 256;                 // 2048 float4 total
            int idx = e4 * 4;
            int ii = idx >> 9;
            int f = idx & 511;
            *(float4*)&Wc[ii][f] = *(const float4*)&g_WeffT[(size_t)(ic + ii) * 512 + f];
        }
#pragma unroll
        for (int p = 0; p < 2; p++) {
            int e = tid + p * 256;
            int row = e >> 4, ii = e & 15;
            sfc[row][ii] = g_sf[(size_t)(n0 + row) * 256 + ic + ii];
        }
        __syncthreads();

#pragma unroll
        for (int ii = 0; ii < 16; ii++) {
            float w[16];
#pragma unroll
            for (int kk = 0; kk < 16; kk++) w[kk] = Wc[ii][lane + 32 * kk];
            float a0 = sfc[warp * 4 + 0][ii];
            float a1 = sfc[warp * 4 + 1][ii];
            float a2 = sfc[warp * 4 + 2][ii];
            float a3 = sfc[warp * 4 + 3][ii];
#pragma unroll
            for (int kk = 0; kk < 16; kk++) {
                acc[0][kk] = fmaf(a0, w[kk], acc[0][kk]);
                acc[1][kk] = fmaf(a1, w[kk], acc[1][kk]);
                acc[2][kk] = fmaf(a2, w[kk], acc[2][kk]);
                acc[3][kk] = fmaf(a3, w[kk], acc[3][kk]);
            }
        }
    }

    float be[16], gg[16], bb[16];
#pragma unroll
    for (int kk = 0; kk < 16; kk++) {
        int f = lane + 32 * kk;
        be[kk] = g_beff[f];
        gg[kk] = ln_g[f];
        bb[kk] = ln_b[f];
    }

#pragma unroll
    for (int r = 0; r < 4; r++) {
        float y[16];
        float s = 0.f;
#pragma unroll
        for (int kk = 0; kk < 16; kk++) {
            y[kk] = acc[r][kk] + be[kk];
            s += y[kk];
        }
#pragma unroll
        for (int o = 16; o > 0; o >>= 1) s += __shfl_xor_sync(0xffffffffu, s, o);
        float mu = s * (1.f / 512.f);
        float sq = 0.f;
#pragma unroll
        for (int kk = 0; kk < 16; kk++) {
            float d = y[kk] - mu;
            sq = fmaf(d, d, sq);
        }
#pragma unroll
        for (int o = 16; o > 0; o >>= 1) sq += __shfl_xor_sync(0xffffffffu, sq, o);
        float rinv = rsqrtf(sq * (1.f / 512.f) + 1e-5f);

        int n = n0 + warp * 4 + r;
#pragma unroll
        for (int kk = 0; kk < 16; kk++) {
            float v = fmaf((y[kk] - mu) * rinv, gg[kk], bb[kk]);
            out[(size_t)n * 512 + lane + 32 * kk] = fmaxf(v, 0.f);
        }
    }
}

// ---------------- launch ----------------
extern "C" void kernel_launch(void* const* d_in, const int* in_sizes, int n_in,
                              void* d_out, int out_size) {
    const float* x    = (const float*)d_in[0];
    const float* W1   = (const float*)d_in[1];
    const float* b1   = (const float*)d_in[2];
    const float* W2   = (const float*)d_in[3];
    const float* b2   = (const float*)d_in[4];
    const float* Wf   = (const float*)d_in[5];
    const float* bf   = (const float*)d_in[6];
    const float* Wfu  = (const float*)d_in[7];
    const float* bfu  = (const float*)d_in[8];
    const float* ln_g = (const float*)d_in[9];
    const float* ln_b = (const float*)d_in[10];
    float* out = (float*)d_out;

    k_w2t<<<(SU_DIM * H1_DIM) / 256, 256>>>(W2);
    k_wefft<<<F_DIM, 256>>>(Wfu, Wf);
    k_beff<<<1, 512>>>(Wfu, bf, bfu);
    k_gemm1<<<dim3(H1_DIM / K1_BN, N_ROWS / K1_BM), 256>>>(x, W1, b1);
    k_spk1<<<(N_ROWS * H1_DIM) / 256, 256>>>(b1);
    k_spike2<<<dim3(N_ROWS / 16, 4), 32>>>(b2);
    k_final<<<N_ROWS / 32, 256>>>(ln_g, ln_b, out);
}

// round 3
// speedup vs baseline: 2.7350x; 2.7350x over previous
#include <cuda_runtime.h>

#define N_ROWS 8192
#define F_DIM  512
#define H1_DIM 512
#define SU_DIM 256
#define T_STEPS 16
#define BETA_F 0.95f
#define THR_F  1.0f

// ---------------- scratch (static device globals; no allocations) ----------------
__device__ float    g_cur0[N_ROWS * H1_DIM];                   // 16 MB
__device__ unsigned g_spk1[N_ROWS * T_STEPS * (H1_DIM / 32)];  // 8 MB  [n][t][w]
__device__ float    g_sf[N_ROWS * SU_DIM];                     // 8 MB
__device__ float    g_W2T[H1_DIM * SU_DIM];                    // [j][i]
__device__ float    g_WeffT[SU_DIM * F_DIM];                   // [i][f]
__device__ float    g_beff[F_DIM];

// ---------------- small prep kernels ----------------
__global__ __launch_bounds__(256) void k_w2t(const float* __restrict__ W2) {
    int idx = blockIdx.x * 256 + threadIdx.x;   // idx < 256*512
    int i = idx >> 9;
    int j = idx & 511;
    g_W2T[j * SU_DIM + i] = W2[idx];
}

// WeffT[i][f] = sum_l Wfu[f][l] * Wf[l][i] + Wfu[f][256+i]
__global__ __launch_bounds__(256) void k_wefft(const float* __restrict__ Wfu,
                                               const float* __restrict__ Wf) {
    __shared__ float wrow[256];
    int f = blockIdx.x;          // 0..511
    int i = threadIdx.x;         // 0..255
    wrow[i] = Wfu[f * 512 + i];
    __syncthreads();
    float acc = Wfu[f * 512 + 256 + i];
#pragma unroll 4
    for (int l = 0; l < 256; l++)
        acc = fmaf(wrow[l], Wf[l * 256 + i], acc);
    g_WeffT[i * 512 + f] = acc;
}

// beff[f] = sum_l Wfu[f][l]*bf[l] + bfu[f]
__global__ __launch_bounds__(512) void k_beff(const float* __restrict__ Wfu,
                                              const float* __restrict__ bf,
                                              const float* __restrict__ bfu) {
    int f = threadIdx.x;  // 512 threads, 1 block
    float acc = bfu[f];
#pragma unroll 4
    for (int l = 0; l < 256; l++)
        acc = fmaf(Wfu[f * 512 + l], bf[l], acc);
    g_beff[f] = acc;
}

// ---------------- K1: cur0 = X @ W1^T + b1  (fp32 tiled GEMM, NT form) ----------------
#define K1_BM 128
#define K1_BN 128
#define K1_BK 16
#define K1_LDS 136

__global__ __launch_bounds__(256) void k_gemm1(const float* __restrict__ X,
                                               const float* __restrict__ W1,
                                               const float* __restrict__ b1) {
    __shared__ float As[K1_BK][K1_LDS];
    __shared__ float Bs[K1_BK][K1_LDS];

    const int n0 = blockIdx.y * K1_BM;
    const int h0 = blockIdx.x * K1_BN;
    const int tid = threadIdx.x;
    const int ty = tid >> 4;        // 0..15 -> row group
    const int tx = tid & 15;        // 0..15 -> col group

    float acc[8][8];
#pragma unroll
    for (int i = 0; i < 8; i++)
#pragma unroll
        for (int j = 0; j < 8; j++) acc[i][j] = 0.f;

    for (int k0 = 0; k0 < 512; k0 += K1_BK) {
#pragma unroll
        for (int p = 0; p < 2; p++) {
            int q = tid + p * 256;          // float4 tile index (512 total per operand)
            int row = q >> 2;
            int kq = q & 3;
            float4 av = *(const float4*)(X + (size_t)(n0 + row) * 512 + k0 + kq * 4);
            As[kq * 4 + 0][row] = av.x;
            As[kq * 4 + 1][row] = av.y;
            As[kq * 4 + 2][row] = av.z;
            As[kq * 4 + 3][row] = av.w;
            float4 bv = *(const float4*)(W1 + (size_t)(h0 + row) * 512 + k0 + kq * 4);
            Bs[kq * 4 + 0][row] = bv.x;
            Bs[kq * 4 + 1][row] = bv.y;
            Bs[kq * 4 + 2][row] = bv.z;
            Bs[kq * 4 + 3][row] = bv.w;
        }
        __syncthreads();
#pragma unroll
        for (int k = 0; k < K1_BK; k++) {
            float a[8], b[8];
            *(float4*)(a)     = *(const float4*)&As[k][ty * 8];
            *(float4*)(a + 4) = *(const float4*)&As[k][ty * 8 + 4];
            *(float4*)(b)     = *(const float4*)&Bs[k][tx * 8];
            *(float4*)(b + 4) = *(const float4*)&Bs[k][tx * 8 + 4];
#pragma unroll
            for (int i = 0; i < 8; i++)
#pragma unroll
                for (int j = 0; j < 8; j++)
                    acc[i][j] = fmaf(a[i], b[j], acc[i][j]);
        }
        __syncthreads();
    }

    float bv[8];
#pragma unroll
    for (int j = 0; j < 8; j++) bv[j] = b1[h0 + tx * 8 + j];

#pragma unroll
    for (int i = 0; i < 8; i++) {
        float4 o0, o1;
        o0.x = acc[i][0] + bv[0]; o0.y = acc[i][1] + bv[1];
        o0.z = acc[i][2] + bv[2]; o0.w = acc[i][3] + bv[3];
        o1.x = acc[i][4] + bv[4]; o1.y = acc[i][5] + bv[5];
        o1.z = acc[i][6] + bv[6]; o1.w = acc[i][7] + bv[7];
        size_t base = (size_t)(n0 + ty * 8 + i) * 512 + h0 + tx * 8;
        *(float4*)(g_cur0 + base)     = o0;
        *(float4*)(g_cur0 + base + 4) = o1;
    }
}

// ---------------- K2: precompute spk1 bitmasks for all 16 steps ----------------
__global__ __launch_bounds__(256) void k_spk1(const float* __restrict__ b1) {
    int idx = blockIdx.x * 256 + threadIdx.x;   // n*512 + j
    int n = idx >> 9;
    int j = idx & 511;
    int lane = threadIdx.x & 31;

    float c0 = g_cur0[idx];
    float bj = b1[j];
    float mem = 0.f;
    float spk = 0.f;
    unsigned myword = 0;
#pragma unroll
    for (int t = 0; t < T_STEPS; t++) {
        float cur = (t == 0) ? c0 : bj;
        mem = fmaf(BETA_F, mem, cur) - spk;
        bool s = (mem - THR_F) > 0.f;
        spk = s ? THR_F : 0.f;
        unsigned w = __ballot_sync(0xffffffffu, s);
        if (lane == t) myword = w;
    }
    if (lane < 16) {
        int w = j >> 5;   // warp-uniform word index 0..15
        g_spk1[((size_t)n * 16 + lane) * 16 + w] = myword;
    }
}

// ---------------- K3: sparse spike-driven layer-2 loop -> spike_features ----------------
// 256 threads (thread = output column i), 16 token rows per block.
// Per step: (1) expand spike bitmasks into an explicit shared event list
// (popc + shfl prefix scan), (2) accumulate with 8-way independent loads (MLP=8).
__global__ __launch_bounds__(256) void k_spike2(const float* __restrict__ b2) {
    __shared__ unsigned short lists[16][512];   // event j-indices per row
    __shared__ int counts[16];

    const int tid = threadIdx.x;
    const int i = tid;                  // output column
    const int n0 = blockIdx.x * 16;
    const float b2i = b2[i];

    // builder role: thread (r_, w_) expands word w_ of row r_
    const int r_ = tid >> 4;
    const int w_ = tid & 15;
    const int sub = tid & 15;           // lane index within 16-wide segment

    float mem2[16], cnt[16];
#pragma unroll
    for (int r = 0; r < 16; r++) { mem2[r] = 0.f; cnt[r] = 0.f; }
    unsigned spkprev = 0;

    for (int t = 0; t < T_STEPS; t++) {
        __syncthreads();   // previous iteration's readers done with lists

        // ---- phase 1: build event lists ----
        unsigned word = g_spk1[((size_t)(n0 + r_) * 16 + t) * 16 + w_];
        int pc = __popc(word);
        int inc = pc;
#pragma unroll
        for (int off = 1; off < 16; off <<= 1) {
            int v = __shfl_up_sync(0xffffffffu, inc, off);
            if (sub >= off) inc += v;
        }
        int base = inc - pc;
        if (sub == 15) counts[r_] = inc;
        while (word) {
            int b = __ffs(word) - 1;
            word &= word - 1;
            lists[r_][base++] = (unsigned short)(w_ * 32 + b);
        }
        __syncthreads();

        // ---- phase 2: accumulate with deep MLP ----
#pragma unroll
        for (int r = 0; r < 16; r++) {
            float cur = b2i;
            const int ne = counts[r];
            int k = 0;
            for (; k + 8 <= ne; k += 8) {
                int j0 = lists[r][k + 0];
                int j1 = lists[r][k + 1];
                int j2 = lists[r][k + 2];
                int j3 = lists[r][k + 3];
                int j4 = lists[r][k + 4];
                int j5 = lists[r][k + 5];
                int j6 = lists[r][k + 6];
                int j7 = lists[r][k + 7];
                float v0 = __ldg(&g_W2T[j0 * SU_DIM + i]);
                float v1 = __ldg(&g_W2T[j1 * SU_DIM + i]);
                float v2 = __ldg(&g_W2T[j2 * SU_DIM + i]);
                float v3 = __ldg(&g_W2T[j3 * SU_DIM + i]);
                float v4 = __ldg(&g_W2T[j4 * SU_DIM + i]);
                float v5 = __ldg(&g_W2T[j5 * SU_DIM + i]);
                float v6 = __ldg(&g_W2T[j6 * SU_DIM + i]);
                float v7 = __ldg(&g_W2T[j7 * SU_DIM + i]);
                cur += ((v0 + v1) + (v2 + v3)) + ((v4 + v5) + (v6 + v7));
            }
            for (; k < ne; k++)
                cur += __ldg(&g_W2T[lists[r][k] * SU_DIM + i]);

            float mm = fmaf(BETA_F, mem2[r], cur) - (((spkprev >> r) & 1u) ? THR_F : 0.f);
            mem2[r] = mm;
            bool s = (mm - THR_F) > 0.f;
            spkprev = (spkprev & ~(1u << r)) | ((unsigned)s << r);
            cnt[r] += s ? 1.f : 0.f;
        }
    }

#pragma unroll
    for (int r = 0; r < 16; r++)
        g_sf[(size_t)(n0 + r) * SU_DIM + i] = cnt[r] * (1.f / 16.f);
}

// ---------------- K4: y = sf @ Weff^T + beff, LayerNorm, ReLU ----------------
// Block: 256 threads = 8 warps; 32 rows per block; warp owns 4 rows x full 512 cols.
__global__ __launch_bounds__(256) void k_final(const float* __restrict__ ln_g,
                                               const float* __restrict__ ln_b,
                                               float* __restrict__ out) {
    __shared__ float Wc[16][512];    // 32 KB   chunk of WeffT
    __shared__ float sfc[32][16];    // 2 KB

    const int tid = threadIdx.x;
    const int warp = tid >> 5;
    const int lane = tid & 31;
    const int n0 = blockIdx.x * 32;

    float acc[4][16];
#pragma unroll
    for (int r = 0; r < 4; r++)
#pragma unroll
        for (int kk = 0; kk < 16; kk++) acc[r][kk] = 0.f;

    for (int ic = 0; ic < 256; ic += 16) {
        __syncthreads();
#pragma unroll
        for (int p = 0; p < 8; p++) {
            int e4 = tid + p * 256;                 // 2048 float4 total
            int idx = e4 * 4;
            int ii = idx >> 9;
            int f = idx & 511;
            *(float4*)&Wc[ii][f] = *(const float4*)&g_WeffT[(size_t)(ic + ii) * 512 + f];
        }
#pragma unroll
        for (int p = 0; p < 2; p++) {
            int e = tid + p * 256;
            int row = e >> 4, ii = e & 15;
            sfc[row][ii] = g_sf[(size_t)(n0 + row) * 256 + ic + ii];
        }
        __syncthreads();

#pragma unroll
        for (int ii = 0; ii < 16; ii++) {
            float w[16];
#pragma unroll
            for (int kk = 0; kk < 16; kk++) w[kk] = Wc[ii][lane + 32 * kk];
            float a0 = sfc[warp * 4 + 0][ii];
            float a1 = sfc[warp * 4 + 1][ii];
            float a2 = sfc[warp * 4 + 2][ii];
            float a3 = sfc[warp * 4 + 3][ii];
#pragma unroll
            for (int kk = 0; kk < 16; kk++) {
                acc[0][kk] = fmaf(a0, w[kk], acc[0][kk]);
                acc[1][kk] = fmaf(a1, w[kk], acc[1][kk]);
                acc[2][kk] = fmaf(a2, w[kk], acc[2][kk]);
                acc[3][kk] = fmaf(a3, w[kk], acc[3][kk]);
            }
        }
    }

    float be[16], gg[16], bb[16];
#pragma unroll
    for (int kk = 0; kk < 16; kk++) {
        int f = lane + 32 * kk;
        be[kk] = g_beff[f];
        gg[kk] = ln_g[f];
        bb[kk] = ln_b[f];
    }

#pragma unroll
    for (int r = 0; r < 4; r++) {
        float y[16];
        float s = 0.f;
#pragma unroll
        for (int kk = 0; kk < 16; kk++) {
            y[kk] = acc[r][kk] + be[kk];
            s += y[kk];
        }
#pragma unroll
        for (int o = 16; o > 0; o >>= 1) s += __shfl_xor_sync(0xffffffffu, s, o);
        float mu = s * (1.f / 512.f);
        float sq = 0.f;
#pragma unroll
        for (int kk = 0; kk < 16; kk++) {
            float d = y[kk] - mu;
            sq = fmaf(d, d, sq);
        }
#pragma unroll
        for (int o = 16; o > 0; o >>= 1) sq += __shfl_xor_sync(0xffffffffu, sq, o);
        float rinv = rsqrtf(sq * (1.f / 512.f) + 1e-5f);

        int n = n0 + warp * 4 + r;
#pragma unroll
        for (int kk = 0; kk < 16; kk++) {
            float v = fmaf((y[kk] - mu) * rinv, gg[kk], bb[kk]);
            out[(size_t)n * 512 + lane + 32 * kk] = fmaxf(v, 0.f);
        }
    }
}

// ---------------- launch ----------------
extern "C" void kernel_launch(void* const* d_in, const int* in_sizes, int n_in,
                              void* d_out, int out_size) {
    const float* x    = (const float*)d_in[0];
    const float* W1   = (const float*)d_in[1];
    const float* b1   = (const float*)d_in[2];
    const float* W2   = (const float*)d_in[3];
    const float* b2   = (const float*)d_in[4];
    const float* Wf   = (const float*)d_in[5];
    const float* bf   = (const float*)d_in[6];
    const float* Wfu  = (const float*)d_in[7];
    const float* bfu  = (const float*)d_in[8];
    const float* ln_g = (const float*)d_in[9];
    const float* ln_b = (const float*)d_in[10];
    float* out = (float*)d_out;

    k_w2t<<<(SU_DIM * H1_DIM) / 256, 256>>>(W2);
    k_wefft<<<F_DIM, 256>>>(Wfu, Wf);
    k_beff<<<1, 512>>>(Wfu, bf, bfu);
    k_gemm1<<<dim3(H1_DIM / K1_BN, N_ROWS / K1_BM), 256>>>(x, W1, b1);
    k_spk1<<<(N_ROWS * H1_DIM) / 256, 256>>>(b1);
    k_spike2<<<N_ROWS / 16, 256>>>(b2);
    k_final<<<N_ROWS / 32, 256>>>(ln_g, ln_b, out);
}

// round 4
// speedup vs baseline: 2.9848x; 1.0913x over previous
#include <cuda_runtime.h>

#define N_ROWS 8192
#define F_DIM  512
#define H1_DIM 512
#define SU_DIM 256
#define T_STEPS 16
#define BETA_F 0.95f
#define THR_F  1.0f

// ---------------- scratch (static device globals; no allocations) ----------------
__device__ unsigned g_spk1[N_ROWS * T_STEPS * (H1_DIM / 32)];  // 8 MB  [n][t][w]
__device__ float    g_sf[N_ROWS * SU_DIM];                     // 8 MB
__device__ float    g_W2T[H1_DIM * SU_DIM];                    // [j][i]
__device__ float    g_WeffT[SU_DIM * F_DIM];                   // [i][f]
__device__ float    g_beff[F_DIM];

// ---------------- small prep kernels ----------------
__global__ __launch_bounds__(256) void k_w2t(const float* __restrict__ W2) {
    int idx = blockIdx.x * 256 + threadIdx.x;   // idx < 256*512
    int i = idx >> 9;
    int j = idx & 511;
    g_W2T[j * SU_DIM + i] = W2[idx];
}

// WeffT[i][f] = sum_l Wfu[f][l] * Wf[l][i] + Wfu[f][256+i]
__global__ __launch_bounds__(256) void k_wefft(const float* __restrict__ Wfu,
                                               const float* __restrict__ Wf) {
    __shared__ float wrow[256];
    int f = blockIdx.x;          // 0..511
    int i = threadIdx.x;         // 0..255
    wrow[i] = Wfu[f * 512 + i];
    __syncthreads();
    float acc = Wfu[f * 512 + 256 + i];
#pragma unroll 4
    for (int l = 0; l < 256; l++)
        acc = fmaf(wrow[l], Wf[l * 256 + i], acc);
    g_WeffT[i * 512 + f] = acc;
}

// beff[f] = sum_l Wfu[f][l]*bf[l] + bfu[f]
__global__ __launch_bounds__(512) void k_beff(const float* __restrict__ Wfu,
                                              const float* __restrict__ bf,
                                              const float* __restrict__ bfu) {
    int f = threadIdx.x;  // 512 threads, 1 block
    float acc = bfu[f];
#pragma unroll 4
    for (int l = 0; l < 256; l++)
        acc = fmaf(Wfu[f * 512 + l], bf[l], acc);
    g_beff[f] = acc;
}

// ---------------- K1: cur0 = X @ W1^T + b1, FUSED 16-step spike recurrence ----------------
// Output: spike bitmasks g_spk1[n][t][w] only (no cur0 materialization).
#define K1_BM 128
#define K1_BN 128
#define K1_BK 16
#define K1_LDS 136

__global__ __launch_bounds__(256) void k_gemm1(const float* __restrict__ X,
                                               const float* __restrict__ W1,
                                               const float* __restrict__ b1) {
    // union: mainloop uses As/Bs (17408 B); epilogue reuses as byte-pack buffer (32768 B)
    __shared__ __align__(16) unsigned char sm[128 * 16 * 16];
    float (*As)[K1_LDS] = (float (*)[K1_LDS])sm;
    float (*Bs)[K1_LDS] = (float (*)[K1_LDS])(sm + K1_BK * K1_LDS * 4);
    unsigned char (*pk)[16][16] = (unsigned char (*)[16][16])sm;  // [row128][t][byte]

    const int n0 = blockIdx.y * K1_BM;
    const int h0 = blockIdx.x * K1_BN;
    const int tid = threadIdx.x;
    const int ty = tid >> 4;        // 0..15 -> row group
    const int tx = tid & 15;        // 0..15 -> col group

    float acc[8][8];
#pragma unroll
    for (int i = 0; i < 8; i++)
#pragma unroll
        for (int j = 0; j < 8; j++) acc[i][j] = 0.f;

    for (int k0 = 0; k0 < 512; k0 += K1_BK) {
#pragma unroll
        for (int p = 0; p < 2; p++) {
            int q = tid + p * 256;          // float4 tile index (512 total per operand)
            int row = q >> 2;
            int kq = q & 3;
            float4 av = *(const float4*)(X + (size_t)(n0 + row) * 512 + k0 + kq * 4);
            As[kq * 4 + 0][row] = av.x;
            As[kq * 4 + 1][row] = av.y;
            As[kq * 4 + 2][row] = av.z;
            As[kq * 4 + 3][row] = av.w;
            float4 bv = *(const float4*)(W1 + (size_t)(h0 + row) * 512 + k0 + kq * 4);
            Bs[kq * 4 + 0][row] = bv.x;
            Bs[kq * 4 + 1][row] = bv.y;
            Bs[kq * 4 + 2][row] = bv.z;
            Bs[kq * 4 + 3][row] = bv.w;
        }
        __syncthreads();
#pragma unroll
        for (int k = 0; k < K1_BK; k++) {
            float a[8], b[8];
            *(float4*)(a)     = *(const float4*)&As[k][ty * 8];
            *(float4*)(a + 4) = *(const float4*)&As[k][ty * 8 + 4];
            *(float4*)(b)     = *(const float4*)&Bs[k][tx * 8];
            *(float4*)(b + 4) = *(const float4*)&Bs[k][tx * 8 + 4];
#pragma unroll
            for (int i = 0; i < 8; i++)
#pragma unroll
                for (int j = 0; j < 8; j++)
                    acc[i][j] = fmaf(a[i], b[j], acc[i][j]);
        }
        __syncthreads();   // also protects smem reuse below
    }

    float bv[8];
#pragma unroll
    for (int j = 0; j < 8; j++) bv[j] = b1[h0 + tx * 8 + j];

    // --- fused spike recurrence + byte packing ---
#pragma unroll
    for (int i = 0; i < 8; i++) {
        unsigned tmask[8];   // per col j: 16 bits over t
#pragma unroll
        for (int j = 0; j < 8; j++) {
            float c0 = acc[i][j] + bv[j];
            float mem = 0.f, spk = 0.f;
            unsigned bits = 0;
#pragma unroll
            for (int t = 0; t < T_STEPS; t++) {
                float cur = (t == 0) ? c0 : bv[j];
                mem = fmaf(BETA_F, mem, cur) - spk;
                bool s = (mem - THR_F) > 0.f;
                spk = s ? THR_F : 0.f;
                bits |= (unsigned)s << t;
            }
            tmask[j] = bits;
        }
#pragma unroll
        for (int t = 0; t < T_STEPS; t++) {
            unsigned b = 0;
#pragma unroll
            for (int j = 0; j < 8; j++) b |= ((tmask[j] >> t) & 1u) << j;
            pk[ty * 8 + i][t][tx] = (unsigned char)b;
        }
    }
    __syncthreads();

    // readout: 8192 words, coalesced stores
#pragma unroll
    for (int p = 0; p < 32; p++) {
        int q = tid + p * 256;          // 0..8191
        int row = q >> 6;
        int rem = q & 63;
        int t = rem >> 2;
        int w = rem & 3;
        uchar4 b4 = *(const uchar4*)&pk[row][t][w * 4];
        unsigned word = (unsigned)b4.x | ((unsigned)b4.y << 8) |
                        ((unsigned)b4.z << 16) | ((unsigned)b4.w << 24);
        g_spk1[((size_t)(n0 + row) * 16 + t) * 16 + (h0 >> 5) + w] = word;
    }
}

// ---------------- K3: sparse spike-driven layer-2 loop -> spike_features ----------------
// Column-chunked for L1 residency: block = 256 threads = 4 token-groups x 64 cols,
// 16 tokens per block. Per-block W2T slice = 512 x 64 x 4B = 128 KB (fits L1).
// Grid (512, 4) ordered chunk-major so co-resident blocks share the slice.
__global__ __launch_bounds__(256) void k_spike2(const float* __restrict__ b2) {
    __shared__ unsigned short lists[16][512];   // event j-indices per row
    __shared__ int counts[16];

    const int tid = threadIdx.x;
    const int n0 = blockIdx.x * 16;
    const int c = tid & 63;
    const int g = tid >> 6;                     // token group 0..3
    const int i = blockIdx.y * 64 + c;          // output column
    const float b2i = b2[i];
    const float* __restrict__ w2col = g_W2T + i;

    // builder role: thread (r_, w_) expands word w_ of row r_
    const int r_ = tid >> 4;
    const int w_ = tid & 15;
    const int sub = tid & 15;

    float mem2[4], cnt[4];
#pragma unroll
    for (int r = 0; r < 4; r++) { mem2[r] = 0.f; cnt[r] = 0.f; }
    unsigned spkprev = 0;

    for (int t = 0; t < T_STEPS; t++) {
        __syncthreads();   // previous iteration's readers done with lists

        // ---- phase 1: build event lists ----
        unsigned word = g_spk1[((size_t)(n0 + r_) * 16 + t) * 16 + w_];
        int pc = __popc(word);
        int inc = pc;
#pragma unroll
        for (int off = 1; off < 16; off <<= 1) {
            int v = __shfl_up_sync(0xffffffffu, inc, off);
            if (sub >= off) inc += v;
        }
        int base = inc - pc;
        if (sub == 15) counts[r_] = inc;
        while (word) {
            int b = __ffs(word) - 1;
            word &= word - 1;
            lists[r_][base++] = (unsigned short)(w_ * 32 + b);
        }
        __syncthreads();

        // ---- phase 2: accumulate, 4 rows/thread, MLP=8 per row ----
#pragma unroll
        for (int rr = 0; rr < 4; rr++) {
            const int r = g * 4 + rr;
            float cur = b2i;
            const int ne = counts[r];
            int k = 0;
            for (; k + 8 <= ne; k += 8) {
                int j0 = lists[r][k + 0];
                int j1 = lists[r][k + 1];
                int j2 = lists[r][k + 2];
                int j3 = lists[r][k + 3];
                int j4 = lists[r][k + 4];
                int j5 = lists[r][k + 5];
                int j6 = lists[r][k + 6];
                int j7 = lists[r][k + 7];
                float v0 = __ldg(w2col + j0 * SU_DIM);
                float v1 = __ldg(w2col + j1 * SU_DIM);
                float v2 = __ldg(w2col + j2 * SU_DIM);
                float v3 = __ldg(w2col + j3 * SU_DIM);
                float v4 = __ldg(w2col + j4 * SU_DIM);
                float v5 = __ldg(w2col + j5 * SU_DIM);
                float v6 = __ldg(w2col + j6 * SU_DIM);
                float v7 = __ldg(w2col + j7 * SU_DIM);
                cur += ((v0 + v1) + (v2 + v3)) + ((v4 + v5) + (v6 + v7));
            }
            for (; k < ne; k++)
                cur += __ldg(w2col + lists[r][k] * SU_DIM);

            float mm = fmaf(BETA_F, mem2[rr], cur) - (((spkprev >> rr) & 1u) ? THR_F : 0.f);
            mem2[rr] = mm;
            bool s = (mm - THR_F) > 0.f;
            spkprev = (spkprev & ~(1u << rr)) | ((unsigned)s << rr);
            cnt[rr] += s ? 1.f : 0.f;
        }
    }

#pragma unroll
    for (int rr = 0; rr < 4; rr++)
        g_sf[(size_t)(n0 + g * 4 + rr) * SU_DIM + i] = cnt[rr] * (1.f / 16.f);
}

// ---------------- K4: y = sf @ Weff^T + beff, LayerNorm, ReLU ----------------
// Block: 256 threads = 8 warps; 32 rows per block; warp owns 4 rows x full 512 cols.
__global__ __launch_bounds__(256) void k_final(const float* __restrict__ ln_g,
                                               const float* __restrict__ ln_b,
                                               float* __restrict__ out) {
    __shared__ float Wc[16][512];    // 32 KB   chunk of WeffT
    __shared__ float sfc[32][16];    // 2 KB

    const int tid = threadIdx.x;
    const int warp = tid >> 5;
    const int lane = tid & 31;
    const int n0 = blockIdx.x * 32;

    float acc[4][16];
#pragma unroll
    for (int r = 0; r < 4; r++)
#pragma unroll
        for (int kk = 0; kk < 16; kk++) acc[r][kk] = 0.f;

    for (int ic = 0; ic < 256; ic += 16) {
        __syncthreads();
#pragma unroll
        for (int p = 0; p < 8; p++) {
            int e4 = tid + p * 256;                 // 2048 float4 total
            int idx = e4 * 4;
            int ii = idx >> 9;
            int f = idx & 511;
            *(float4*)&Wc[ii][f] = *(const float4*)&g_WeffT[(size_t)(ic + ii) * 512 + f];
        }
#pragma unroll
        for (int p = 0; p < 2; p++) {
            int e = tid + p * 256;
            int row = e >> 4, ii = e & 15;
            sfc[row][ii] = g_sf[(size_t)(n0 + row) * 256 + ic + ii];
        }
        __syncthreads();

#pragma unroll
        for (int ii = 0; ii < 16; ii++) {
            float w[16];
#pragma unroll
            for (int kk = 0; kk < 16; kk++) w[kk] = Wc[ii][lane + 32 * kk];
            float a0 = sfc[warp * 4 + 0][ii];
            float a1 = sfc[warp * 4 + 1][ii];
            float a2 = sfc[warp * 4 + 2][ii];
            float a3 = sfc[warp * 4 + 3][ii];
#pragma unroll
            for (int kk = 0; kk < 16; kk++) {
                acc[0][kk] = fmaf(a0, w[kk], acc[0][kk]);
                acc[1][kk] = fmaf(a1, w[kk], acc[1][kk]);
                acc[2][kk] = fmaf(a2, w[kk], acc[2][kk]);
                acc[3][kk] = fmaf(a3, w[kk], acc[3][kk]);
            }
        }
    }

    float be[16], gg[16], bb[16];
#pragma unroll
    for (int kk = 0; kk < 16; kk++) {
        int f = lane + 32 * kk;
        be[kk] = g_beff[f];
        gg[kk] = ln_g[f];
        bb[kk] = ln_b[f];
    }

#pragma unroll
    for (int r = 0; r < 4; r++) {
        float y[16];
        float s = 0.f;
#pragma unroll
        for (int kk = 0; kk < 16; kk++) {
            y[kk] = acc[r][kk] + be[kk];
            s += y[kk];
        }
#pragma unroll
        for (int o = 16; o > 0; o >>= 1) s += __shfl_xor_sync(0xffffffffu, s, o);
        float mu = s * (1.f / 512.f);
        float sq = 0.f;
#pragma unroll
        for (int kk = 0; kk < 16; kk++) {
            float d = y[kk] - mu;
            sq = fmaf(d, d, sq);
        }
#pragma unroll
        for (int o = 16; o > 0; o >>= 1) sq += __shfl_xor_sync(0xffffffffu, sq, o);
        float rinv = rsqrtf(sq * (1.f / 512.f) + 1e-5f);

        int n = n0 + warp * 4 + r;
#pragma unroll
        for (int kk = 0; kk < 16; kk++) {
            float v = fmaf((y[kk] - mu) * rinv, gg[kk], bb[kk]);
            out[(size_t)n * 512 + lane + 32 * kk] = fmaxf(v, 0.f);
        }
    }
}

// ---------------- launch ----------------
extern "C" void kernel_launch(void* const* d_in, const int* in_sizes, int n_in,
                              void* d_out, int out_size) {
    const float* x    = (const float*)d_in[0];
    const float* W1   = (const float*)d_in[1];
    const float* b1   = (const float*)d_in[2];
    const float* W2   = (const float*)d_in[3];
    const float* b2   = (const float*)d_in[4];
    const float* Wf   = (const float*)d_in[5];
    const float* bf   = (const float*)d_in[6];
    const float* Wfu  = (const float*)d_in[7];
    const float* bfu  = (const float*)d_in[8];
    const float* ln_g = (const float*)d_in[9];
    const float* ln_b = (const float*)d_in[10];
    float* out = (float*)d_out;

    k_w2t<<<(SU_DIM * H1_DIM) / 256, 256>>>(W2);
    k_wefft<<<F_DIM, 256>>>(Wfu, Wf);
    k_beff<<<1, 512>>>(Wfu, bf, bfu);
    k_gemm1<<<dim3(H1_DIM / K1_BN, N_ROWS / K1_BM), 256>>>(x, W1, b1);
    k_spike2<<<dim3(N_ROWS / 16, 4), 256>>>(b2);
    k_final<<<N_ROWS / 32, 256>>>(ln_g, ln_b, out);
}

// round 5
// speedup vs baseline: 3.2846x; 1.1004x over previous
#include <cuda_runtime.h>

#define N_ROWS 8192
#define F_DIM  512
#define H1_DIM 512
#define SU_DIM 256
#define T_STEPS 16
#define BETA_F 0.95f
#define THR_F  1.0f

// ---------------- scratch (static device globals; no allocations) ----------------
__device__ unsigned g_spk1[N_ROWS * T_STEPS * (H1_DIM / 32)];  // 8 MB  [n][t][w]
__device__ float    g_sf[N_ROWS * SU_DIM];                     // 8 MB
__device__ float    g_W2T[H1_DIM * SU_DIM];                    // [j][i]
__device__ float    g_WeffT[SU_DIM * F_DIM];                   // [i][f]
__device__ float    g_beff[F_DIM];

// ---------------- fused prep: w2t (blocks 512..1023), wefft (0..511), beff (1024) ----
__global__ __launch_bounds__(256) void k_prep(const float* __restrict__ W2,
                                              const float* __restrict__ Wfu,
                                              const float* __restrict__ Wf,
                                              const float* __restrict__ bf,
                                              const float* __restrict__ bfu) {
    int bid = blockIdx.x;
    if (bid < 512) {
        // WeffT[i][f] = sum_l Wfu[f][l] * Wf[l][i] + Wfu[f][256+i]
        __shared__ float wrow[256];
        int f = bid;
        int i = threadIdx.x;
        wrow[i] = Wfu[f * 512 + i];
        __syncthreads();
        float acc = Wfu[f * 512 + 256 + i];
#pragma unroll 4
        for (int l = 0; l < 256; l++)
            acc = fmaf(wrow[l], Wf[l * 256 + i], acc);
        g_WeffT[i * 512 + f] = acc;
    } else if (bid < 1024) {
        int idx = (bid - 512) * 256 + threadIdx.x;  // < 256*512
        int i = idx >> 9;
        int j = idx & 511;
        g_W2T[j * SU_DIM + i] = W2[idx];
    } else {
        // beff[f] = sum_l Wfu[f][l]*bf[l] + bfu[f]   (2 f per thread)
#pragma unroll
        for (int p = 0; p < 2; p++) {
            int f = threadIdx.x + p * 256;
            float acc = bfu[f];
#pragma unroll 4
            for (int l = 0; l < 256; l++)
                acc = fmaf(Wfu[f * 512 + l], bf[l], acc);
            g_beff[f] = acc;
        }
    }
}

// ---------------- K1: cur0 = X @ W1^T + b1, FUSED 16-step spike recurrence ----------------
// Output: spike bitmasks g_spk1[n][t][w] only (no cur0 materialization).
#define K1_BM 128
#define K1_BN 128
#define K1_BK 16
#define K1_LDS 136

__global__ __launch_bounds__(256, 2) void k_gemm1(const float* __restrict__ X,
                                                  const float* __restrict__ W1,
                                                  const float* __restrict__ b1) {
    // union: mainloop uses As/Bs (17408 B); epilogue reuses as byte-pack buffer (32768 B)
    __shared__ __align__(16) unsigned char sm[128 * 16 * 16];
    float (*As)[K1_LDS] = (float (*)[K1_LDS])sm;
    float (*Bs)[K1_LDS] = (float (*)[K1_LDS])(sm + K1_BK * K1_LDS * 4);
    unsigned char (*pk)[16][16] = (unsigned char (*)[16][16])sm;  // [row128][t][byte]

    const int n0 = blockIdx.y * K1_BM;
    const int h0 = blockIdx.x * K1_BN;
    const int tid = threadIdx.x;
    const int ty = tid >> 4;        // 0..15 -> row group
    const int tx = tid & 15;        // 0..15 -> col group

    float acc[8][8];
#pragma unroll
    for (int i = 0; i < 8; i++)
#pragma unroll
        for (int j = 0; j < 8; j++) acc[i][j] = 0.f;

    for (int k0 = 0; k0 < 512; k0 += K1_BK) {
#pragma unroll
        for (int p = 0; p < 2; p++) {
            int q = tid + p * 256;          // float4 tile index (512 total per operand)
            int row = q >> 2;
            int kq = q & 3;
            float4 av = *(const float4*)(X + (size_t)(n0 + row) * 512 + k0 + kq * 4);
            As[kq * 4 + 0][row] = av.x;
            As[kq * 4 + 1][row] = av.y;
            As[kq * 4 + 2][row] = av.z;
            As[kq * 4 + 3][row] = av.w;
            float4 bv = *(const float4*)(W1 + (size_t)(h0 + row) * 512 + k0 + kq * 4);
            Bs[kq * 4 + 0][row] = bv.x;
            Bs[kq * 4 + 1][row] = bv.y;
            Bs[kq * 4 + 2][row] = bv.z;
            Bs[kq * 4 + 3][row] = bv.w;
        }
        __syncthreads();
#pragma unroll
        for (int k = 0; k < K1_BK; k++) {
            float a[8], b[8];
            *(float4*)(a)     = *(const float4*)&As[k][ty * 8];
            *(float4*)(a + 4) = *(const float4*)&As[k][ty * 8 + 4];
            *(float4*)(b)     = *(const float4*)&Bs[k][tx * 8];
            *(float4*)(b + 4) = *(const float4*)&Bs[k][tx * 8 + 4];
#pragma unroll
            for (int i = 0; i < 8; i++)
#pragma unroll
                for (int j = 0; j < 8; j++)
                    acc[i][j] = fmaf(a[i], b[j], acc[i][j]);
        }
        __syncthreads();   // also protects smem reuse below
    }

    float bv[8];
#pragma unroll
    for (int j = 0; j < 8; j++) bv[j] = b1[h0 + tx * 8 + j];

    // --- fused spike recurrence + byte packing (low live-reg version) ---
#pragma unroll
    for (int i = 0; i < 8; i++) {
        unsigned pw[4] = {0u, 0u, 0u, 0u};   // byte per t: pw[t>>2] byte (t&3)
#pragma unroll
        for (int j = 0; j < 8; j++) {
            float c0 = acc[i][j] + bv[j];
            float mem = 0.f, spk = 0.f;
            unsigned bits = 0;
#pragma unroll
            for (int t = 0; t < T_STEPS; t++) {
                float cur = (t == 0) ? c0 : bv[j];
                mem = fmaf(BETA_F, mem, cur) - spk;
                bool s = (mem - THR_F) > 0.f;
                spk = s ? THR_F : 0.f;
                bits |= (unsigned)s << t;
            }
#pragma unroll
            for (int q = 0; q < 4; q++) {
#pragma unroll
                for (int s2 = 0; s2 < 4; s2++)
                    pw[q] |= ((bits >> (q * 4 + s2)) & 1u) << (s2 * 8 + j);
            }
        }
#pragma unroll
        for (int t = 0; t < T_STEPS; t++)
            pk[ty * 8 + i][t][tx] = (unsigned char)((pw[t >> 2] >> ((t & 3) * 8)) & 0xffu);
    }
    __syncthreads();

    // readout: 8192 words, coalesced stores
#pragma unroll
    for (int p = 0; p < 32; p++) {
        int q = tid + p * 256;          // 0..8191
        int row = q >> 6;
        int rem = q & 63;
        int t = rem >> 2;
        int w = rem & 3;
        uchar4 b4 = *(const uchar4*)&pk[row][t][w * 4];
        unsigned word = (unsigned)b4.x | ((unsigned)b4.y << 8) |
                        ((unsigned)b4.z << 16) | ((unsigned)b4.w << 24);
        g_spk1[((size_t)(n0 + row) * 16 + t) * 16 + (h0 >> 5) + w] = word;
    }
}

// ---------------- K3: sparse spike-driven layer-2 loop -> spike_features ----------------
// Column-chunked for L1 residency: block = 256 threads = 4 token-groups x 64 cols,
// 16 tokens per block. Per-block W2T slice = 512 x 64 x 4B = 128 KB (fits L1).
__global__ __launch_bounds__(256) void k_spike2(const float* __restrict__ b2) {
    __shared__ unsigned short lists[16][512];   // event j-indices per row
    __shared__ int counts[16];

    const int tid = threadIdx.x;
    const int n0 = blockIdx.x * 16;
    const int c = tid & 63;
    const int g = tid >> 6;                     // token group 0..3
    const int i = blockIdx.y * 64 + c;          // output column
    const float b2i = b2[i];
    const float* __restrict__ w2col = g_W2T + i;

    // builder role: thread (r_, w_) expands word w_ of row r_
    const int r_ = tid >> 4;
    const int w_ = tid & 15;
    const int sub = tid & 15;

    float mem2[4], cnt[4];
#pragma unroll
    for (int r = 0; r < 4; r++) { mem2[r] = 0.f; cnt[r] = 0.f; }
    unsigned spkprev = 0;

    for (int t = 0; t < T_STEPS; t++) {
        __syncthreads();   // previous iteration's readers done with lists

        // ---- phase 1: build event lists ----
        unsigned word = g_spk1[((size_t)(n0 + r_) * 16 + t) * 16 + w_];
        int pc = __popc(word);
        int inc = pc;
#pragma unroll
        for (int off = 1; off < 16; off <<= 1) {
            int v = __shfl_up_sync(0xffffffffu, inc, off);
            if (sub >= off) inc += v;
        }
        int base = inc - pc;
        if (sub == 15) counts[r_] = inc;
        while (word) {
            int b = __ffs(word) - 1;
            word &= word - 1;
            lists[r_][base++] = (unsigned short)(w_ * 32 + b);
        }
        __syncthreads();

        // ---- phase 2: accumulate, 4 rows/thread, MLP=8 per row ----
#pragma unroll
        for (int rr = 0; rr < 4; rr++) {
            const int r = g * 4 + rr;
            float cur = b2i;
            const int ne = counts[r];
            int k = 0;
            for (; k + 8 <= ne; k += 8) {
                int j0 = lists[r][k + 0];
                int j1 = lists[r][k + 1];
                int j2 = lists[r][k + 2];
                int j3 = lists[r][k + 3];
                int j4 = lists[r][k + 4];
                int j5 = lists[r][k + 5];
                int j6 = lists[r][k + 6];
                int j7 = lists[r][k + 7];
                float v0 = __ldg(w2col + j0 * SU_DIM);
                float v1 = __ldg(w2col + j1 * SU_DIM);
                float v2 = __ldg(w2col + j2 * SU_DIM);
                float v3 = __ldg(w2col + j3 * SU_DIM);
                float v4 = __ldg(w2col + j4 * SU_DIM);
                float v5 = __ldg(w2col + j5 * SU_DIM);
                float v6 = __ldg(w2col + j6 * SU_DIM);
                float v7 = __ldg(w2col + j7 * SU_DIM);
                cur += ((v0 + v1) + (v2 + v3)) + ((v4 + v5) + (v6 + v7));
            }
            for (; k < ne; k++)
                cur += __ldg(w2col + lists[r][k] * SU_DIM);

            float mm = fmaf(BETA_F, mem2[rr], cur) - (((spkprev >> rr) & 1u) ? THR_F : 0.f);
            mem2[rr] = mm;
            bool s = (mm - THR_F) > 0.f;
            spkprev = (spkprev & ~(1u << rr)) | ((unsigned)s << rr);
            cnt[rr] += s ? 1.f : 0.f;
        }
    }

#pragma unroll
    for (int rr = 0; rr < 4; rr++)
        g_sf[(size_t)(n0 + g * 4 + rr) * SU_DIM + i] = cnt[rr] * (1.f / 16.f);
}

// ---------------- K4: y = sf @ Weff^T + beff, LayerNorm, ReLU ----------------
// Block: 256 threads = 8 warps; 32 rows per block; warp owns 4 rows x full 512 cols.
__global__ __launch_bounds__(256) void k_final(const float* __restrict__ ln_g,
                                               const float* __restrict__ ln_b,
                                               float* __restrict__ out) {
    __shared__ float Wc[16][512];    // 32 KB   chunk of WeffT
    __shared__ float sfc[32][16];    // 2 KB

    const int tid = threadIdx.x;
    const int warp = tid >> 5;
    const int lane = tid & 31;
    const int n0 = blockIdx.x * 32;

    float acc[4][16];
#pragma unroll
    for (int r = 0; r < 4; r++)
#pragma unroll
        for (int kk = 0; kk < 16; kk++) acc[r][kk] = 0.f;

    for (int ic = 0; ic < 256; ic += 16) {
        __syncthreads();
#pragma unroll
        for (int p = 0; p < 8; p++) {
            int e4 = tid + p * 256;                 // 2048 float4 total
            int idx = e4 * 4;
            int ii = idx >> 9;
            int f = idx & 511;
            *(float4*)&Wc[ii][f] = *(const float4*)&g_WeffT[(size_t)(ic + ii) * 512 + f];
        }
#pragma unroll
        for (int p = 0; p < 2; p++) {
            int e = tid + p * 256;
            int row = e >> 4, ii = e & 15;
            sfc[row][ii] = g_sf[(size_t)(n0 + row) * 256 + ic + ii];
        }
        __syncthreads();

#pragma unroll
        for (int ii = 0; ii < 16; ii++) {
            float w[16];
#pragma unroll
            for (int kk = 0; kk < 16; kk++) w[kk] = Wc[ii][lane + 32 * kk];
            float a0 = sfc[warp * 4 + 0][ii];
            float a1 = sfc[warp * 4 + 1][ii];
            float a2 = sfc[warp * 4 + 2][ii];
            float a3 = sfc[warp * 4 + 3][ii];
#pragma unroll
            for (int kk = 0; kk < 16; kk++) {
                acc[0][kk] = fmaf(a0, w[kk], acc[0][kk]);
                acc[1][kk] = fmaf(a1, w[kk], acc[1][kk]);
                acc[2][kk] = fmaf(a2, w[kk], acc[2][kk]);
                acc[3][kk] = fmaf(a3, w[kk], acc[3][kk]);
            }
        }
    }

    float be[16], gg[16], bb[16];
#pragma unroll
    for (int kk = 0; kk < 16; kk++) {
        int f = lane + 32 * kk;
        be[kk] = g_beff[f];
        gg[kk] = ln_g[f];
        bb[kk] = ln_b[f];
    }

#pragma unroll
    for (int r = 0; r < 4; r++) {
        float y[16];
        float s = 0.f;
#pragma unroll
        for (int kk = 0; kk < 16; kk++) {
            y[kk] = acc[r][kk] + be[kk];
            s += y[kk];
        }
#pragma unroll
        for (int o = 16; o > 0; o >>= 1) s += __shfl_xor_sync(0xffffffffu, s, o);
        float mu = s * (1.f / 512.f);
        float sq = 0.f;
#pragma unroll
        for (int kk = 0; kk < 16; kk++) {
            float d = y[kk] - mu;
            sq = fmaf(d, d, sq);
        }
#pragma unroll
        for (int o = 16; o > 0; o >>= 1) sq += __shfl_xor_sync(0xffffffffu, sq, o);
        float rinv = rsqrtf(sq * (1.f / 512.f) + 1e-5f);

        int n = n0 + warp * 4 + r;
#pragma unroll
        for (int kk = 0; kk < 16; kk++) {
            float v = fmaf((y[kk] - mu) * rinv, gg[kk], bb[kk]);
            out[(size_t)n * 512 + lane + 32 * kk] = fmaxf(v, 0.f);
        }
    }
}

// ---------------- launch ----------------
extern "C" void kernel_launch(void* const* d_in, const int* in_sizes, int n_in,
                              void* d_out, int out_size) {
    const float* x    = (const float*)d_in[0];
    const float* W1   = (const float*)d_in[1];
    const float* b1   = (const float*)d_in[2];
    const float* W2   = (const float*)d_in[3];
    const float* b2   = (const float*)d_in[4];
    const float* Wf   = (const float*)d_in[5];
    const float* bf   = (const float*)d_in[6];
    const float* Wfu  = (const float*)d_in[7];
    const float* bfu  = (const float*)d_in[8];
    const float* ln_g = (const float*)d_in[9];
    const float* ln_b = (const float*)d_in[10];
    float* out = (float*)d_out;

    k_prep<<<1025, 256>>>(W2, Wfu, Wf, bf, bfu);
    k_gemm1<<<dim3(H1_DIM / K1_BN, N_ROWS / K1_BM), 256>>>(x, W1, b1);
    k_spike2<<<dim3(N_ROWS / 16, 4), 256>>>(b2);
    k_final<<<N_ROWS / 32, 256>>>(ln_g, ln_b, out);
}

// round 6
// speedup vs baseline: 3.4975x; 1.0648x over previous
#include <cuda_runtime.h>

#define N_ROWS 8192
#define F_DIM  512
#define H1_DIM 512
#define SU_DIM 256
#define T_STEPS 16
#define BETA_F 0.95f
#define THR_F  1.0f

// ---------------- scratch (static device globals; no allocations) ----------------
__device__ unsigned g_spk1[N_ROWS * T_STEPS * (H1_DIM / 32)];  // 8 MB  [n][t][w]
__device__ float    g_sf[N_ROWS * SU_DIM];                     // 8 MB
__device__ float    g_W2T[H1_DIM * SU_DIM];                    // [j][i]
__device__ float    g_WeffT[SU_DIM * F_DIM];                   // [i][f]
__device__ float    g_beff[F_DIM];

// ---------------- fused prep: wefft (0..511), w2t (512..1023), beff (1024) ----
__global__ __launch_bounds__(256) void k_prep(const float* __restrict__ W2,
                                              const float* __restrict__ Wfu,
                                              const float* __restrict__ Wf,
                                              const float* __restrict__ bf,
                                              const float* __restrict__ bfu) {
    int bid = blockIdx.x;
    if (bid < 512) {
        // WeffT[i][f] = sum_l Wfu[f][l] * Wf[l][i] + Wfu[f][256+i]
        __shared__ float wrow[256];
        int f = bid;
        int i = threadIdx.x;
        wrow[i] = Wfu[f * 512 + i];
        __syncthreads();
        float acc = Wfu[f * 512 + 256 + i];
#pragma unroll 4
        for (int l = 0; l < 256; l++)
            acc = fmaf(wrow[l], Wf[l * 256 + i], acc);
        g_WeffT[i * 512 + f] = acc;
    } else if (bid < 1024) {
        int idx = (bid - 512) * 256 + threadIdx.x;  // < 256*512
        int i = idx >> 9;
        int j = idx & 511;
        g_W2T[j * SU_DIM + i] = W2[idx];
    } else {
        // beff[f] = sum_l Wfu[f][l]*bf[l] + bfu[f]   (2 f per thread)
#pragma unroll
        for (int p = 0; p < 2; p++) {
            int f = threadIdx.x + p * 256;
            float acc = bfu[f];
#pragma unroll 4
            for (int l = 0; l < 256; l++)
                acc = fmaf(Wfu[f * 512 + l], bf[l], acc);
            g_beff[f] = acc;
        }
    }
}

// ---------------- K1: cur0 = X @ W1^T + b1, FUSED 16-step spike recurrence ----------------
// Output: spike bitmasks g_spk1[n][t][w] only (no cur0 materialization).
// Software-pipelined: next K-tile is loaded into registers while computing on smem.
#define K1_BM 128
#define K1_BN 128
#define K1_BK 16
#define K1_LDS 136

__global__ __launch_bounds__(256, 2) void k_gemm1(const float* __restrict__ X,
                                                  const float* __restrict__ W1,
                                                  const float* __restrict__ b1) {
    // union: mainloop uses As/Bs (17408 B); epilogue reuses as byte-pack buffer (32768 B)
    __shared__ __align__(16) unsigned char sm[128 * 16 * 16];
    float (*As)[K1_LDS] = (float (*)[K1_LDS])sm;
    float (*Bs)[K1_LDS] = (float (*)[K1_LDS])(sm + K1_BK * K1_LDS * 4);
    unsigned char (*pk)[16][16] = (unsigned char (*)[16][16])sm;  // [row128][t][byte]

    const int n0 = blockIdx.y * K1_BM;
    const int h0 = blockIdx.x * K1_BN;
    const int tid = threadIdx.x;
    const int ty = tid >> 4;        // 0..15 -> row group
    const int tx = tid & 15;        // 0..15 -> col group

    // loader indices (fixed per thread)
    const int lrow0 = tid >> 2;                // q = tid
    const int lkq0  = tid & 3;
    const int lrow1 = (tid + 256) >> 2;        // q = tid + 256
    const int lkq1  = (tid + 256) & 3;

    float4 pa0, pa1, pb0, pb1;
    {
        pa0 = *(const float4*)(X  + (size_t)(n0 + lrow0) * 512 + lkq0 * 4);
        pb0 = *(const float4*)(W1 + (size_t)(h0 + lrow0) * 512 + lkq0 * 4);
        pa1 = *(const float4*)(X  + (size_t)(n0 + lrow1) * 512 + lkq1 * 4);
        pb1 = *(const float4*)(W1 + (size_t)(h0 + lrow1) * 512 + lkq1 * 4);
    }

    float acc[8][8];
#pragma unroll
    for (int i = 0; i < 8; i++)
#pragma unroll
        for (int j = 0; j < 8; j++) acc[i][j] = 0.f;

    for (int k0 = 0; k0 < 512; k0 += K1_BK) {
        // store prefetched tile to smem
        As[lkq0 * 4 + 0][lrow0] = pa0.x;
        As[lkq0 * 4 + 1][lrow0] = pa0.y;
        As[lkq0 * 4 + 2][lrow0] = pa0.z;
        As[lkq0 * 4 + 3][lrow0] = pa0.w;
        Bs[lkq0 * 4 + 0][lrow0] = pb0.x;
        Bs[lkq0 * 4 + 1][lrow0] = pb0.y;
        Bs[lkq0 * 4 + 2][lrow0] = pb0.z;
        Bs[lkq0 * 4 + 3][lrow0] = pb0.w;
        As[lkq1 * 4 + 0][lrow1] = pa1.x;
        As[lkq1 * 4 + 1][lrow1] = pa1.y;
        As[lkq1 * 4 + 2][lrow1] = pa1.z;
        As[lkq1 * 4 + 3][lrow1] = pa1.w;
        Bs[lkq1 * 4 + 0][lrow1] = pb1.x;
        Bs[lkq1 * 4 + 1][lrow1] = pb1.y;
        Bs[lkq1 * 4 + 2][lrow1] = pb1.z;
        Bs[lkq1 * 4 + 3][lrow1] = pb1.w;
        __syncthreads();

        // issue next tile's loads early (latency overlaps compute below)
        if (k0 + K1_BK < 512) {
            int kn = k0 + K1_BK;
            pa0 = *(const float4*)(X  + (size_t)(n0 + lrow0) * 512 + kn + lkq0 * 4);
            pb0 = *(const float4*)(W1 + (size_t)(h0 + lrow0) * 512 + kn + lkq0 * 4);
            pa1 = *(const float4*)(X  + (size_t)(n0 + lrow1) * 512 + kn + lkq1 * 4);
            pb1 = *(const float4*)(W1 + (size_t)(h0 + lrow1) * 512 + kn + lkq1 * 4);
        }

#pragma unroll
        for (int k = 0; k < K1_BK; k++) {
            float a[8], b[8];
            *(float4*)(a)     = *(const float4*)&As[k][ty * 8];
            *(float4*)(a + 4) = *(const float4*)&As[k][ty * 8 + 4];
            *(float4*)(b)     = *(const float4*)&Bs[k][tx * 8];
            *(float4*)(b + 4) = *(const float4*)&Bs[k][tx * 8 + 4];
#pragma unroll
            for (int i = 0; i < 8; i++)
#pragma unroll
                for (int j = 0; j < 8; j++)
                    acc[i][j] = fmaf(a[i], b[j], acc[i][j]);
        }
        __syncthreads();   // also protects smem reuse below
    }

    float bv[8];
#pragma unroll
    for (int j = 0; j < 8; j++) bv[j] = b1[h0 + tx * 8 + j];

    // --- fused spike recurrence + byte packing (low live-reg version) ---
#pragma unroll
    for (int i = 0; i < 8; i++) {
        unsigned pw[4] = {0u, 0u, 0u, 0u};   // byte per t: pw[t>>2] byte (t&3)
#pragma unroll
        for (int j = 0; j < 8; j++) {
            float c0 = acc[i][j] + bv[j];
            float mem = 0.f, spk = 0.f;
            unsigned bits = 0;
#pragma unroll
            for (int t = 0; t < T_STEPS; t++) {
                float cur = (t == 0) ? c0 : bv[j];
                mem = fmaf(BETA_F, mem, cur) - spk;
                bool s = (mem - THR_F) > 0.f;
                spk = s ? THR_F : 0.f;
                bits |= (unsigned)s << t;
            }
#pragma unroll
            for (int q = 0; q < 4; q++) {
#pragma unroll
                for (int s2 = 0; s2 < 4; s2++)
                    pw[q] |= ((bits >> (q * 4 + s2)) & 1u) << (s2 * 8 + j);
            }
        }
#pragma unroll
        for (int t = 0; t < T_STEPS; t++)
            pk[ty * 8 + i][t][tx] = (unsigned char)((pw[t >> 2] >> ((t & 3) * 8)) & 0xffu);
    }
    __syncthreads();

    // readout: 8192 words, coalesced stores
#pragma unroll
    for (int p = 0; p < 32; p++) {
        int q = tid + p * 256;          // 0..8191
        int row = q >> 6;
        int rem = q & 63;
        int t = rem >> 2;
        int w = rem & 3;
        uchar4 b4 = *(const uchar4*)&pk[row][t][w * 4];
        unsigned word = (unsigned)b4.x | ((unsigned)b4.y << 8) |
                        ((unsigned)b4.z << 16) | ((unsigned)b4.w << 24);
        g_spk1[((size_t)(n0 + row) * 16 + t) * 16 + (h0 >> 5) + w] = word;
    }
}

// ---------------- K3: sparse spike-driven layer-2 loop -> spike_features ----------------
// Column-chunked for L1 residency. Block = 256 threads = 8 warps.
// Warp = 32 lanes x 2 columns (full 64-col chunk) and owns 2 token rows.
// Per event: ONE warp-LDG.64 per block (4 chip-wide) instead of 8 warp-LDG.32.
__global__ __launch_bounds__(256) void k_spike2(const float* __restrict__ b2) {
    __shared__ unsigned short lists[16][512];   // event j-indices per row
    __shared__ int counts[16];

    const int tid = threadIdx.x;
    const int n0 = blockIdx.x * 16;
    const int lane = tid & 31;
    const int wp = tid >> 5;                    // warp 0..7 -> rows wp*2, wp*2+1
    const int i0 = blockIdx.y * 64 + lane * 2;  // column pair
    const float2 b2v = *(const float2*)(b2 + i0);
    const float* __restrict__ w2col = g_W2T + i0;

    // builder role: thread (r_, w_) expands word w_ of row r_
    const int r_ = tid >> 4;
    const int w_ = tid & 15;
    const int sub = tid & 15;

    float mx[2], my[2], cntx[2], cnty[2];
#pragma unroll
    for (int r = 0; r < 2; r++) { mx[r] = my[r] = cntx[r] = cnty[r] = 0.f; }
    unsigned spx = 0, spy = 0;

    for (int t = 0; t < T_STEPS; t++) {
        __syncthreads();   // previous iteration's readers done with lists

        // ---- phase 1: build event lists ----
        unsigned word = g_spk1[((size_t)(n0 + r_) * 16 + t) * 16 + w_];
        int pc = __popc(word);
        int inc = pc;
#pragma unroll
        for (int off = 1; off < 16; off <<= 1) {
            int v = __shfl_up_sync(0xffffffffu, inc, off);
            if (sub >= off) inc += v;
        }
        int base = inc - pc;
        if (sub == 15) counts[r_] = inc;
        while (word) {
            int b = __ffs(word) - 1;
            word &= word - 1;
            lists[r_][base++] = (unsigned short)(w_ * 32 + b);
        }
        __syncthreads();

        // ---- phase 2: accumulate, 2 rows/warp, float2/thread, MLP=8 ----
#pragma unroll
        for (int rr = 0; rr < 2; rr++) {
            const int r = wp * 2 + rr;
            float cx = b2v.x, cy = b2v.y;
            const int ne = counts[r];
            int k = 0;
            for (; k + 8 <= ne; k += 8) {
                int j0 = lists[r][k + 0];
                int j1 = lists[r][k + 1];
                int j2 = lists[r][k + 2];
                int j3 = lists[r][k + 3];
                int j4 = lists[r][k + 4];
                int j5 = lists[r][k + 5];
                int j6 = lists[r][k + 6];
                int j7 = lists[r][k + 7];
                float2 v0 = __ldg((const float2*)(w2col + j0 * SU_DIM));
                float2 v1 = __ldg((const float2*)(w2col + j1 * SU_DIM));
                float2 v2 = __ldg((const float2*)(w2col + j2 * SU_DIM));
                float2 v3 = __ldg((const float2*)(w2col + j3 * SU_DIM));
                float2 v4 = __ldg((const float2*)(w2col + j4 * SU_DIM));
                float2 v5 = __ldg((const float2*)(w2col + j5 * SU_DIM));
                float2 v6 = __ldg((const float2*)(w2col + j6 * SU_DIM));
                float2 v7 = __ldg((const float2*)(w2col + j7 * SU_DIM));
                cx += ((v0.x + v1.x) + (v2.x + v3.x)) + ((v4.x + v5.x) + (v6.x + v7.x));
                cy += ((v0.y + v1.y) + (v2.y + v3.y)) + ((v4.y + v5.y) + (v6.y + v7.y));
            }
            for (; k < ne; k++) {
                float2 v = __ldg((const float2*)(w2col + lists[r][k] * SU_DIM));
                cx += v.x;
                cy += v.y;
            }

            float mmx = fmaf(BETA_F, mx[rr], cx) - (((spx >> rr) & 1u) ? THR_F : 0.f);
            float mmy = fmaf(BETA_F, my[rr], cy) - (((spy >> rr) & 1u) ? THR_F : 0.f);
            mx[rr] = mmx;
            my[rr] = mmy;
            bool sx = (mmx - THR_F) > 0.f;
            bool sy = (mmy - THR_F) > 0.f;
            spx = (spx & ~(1u << rr)) | ((unsigned)sx << rr);
            spy = (spy & ~(1u << rr)) | ((unsigned)sy << rr);
            cntx[rr] += sx ? 1.f : 0.f;
            cnty[rr] += sy ? 1.f : 0.f;
        }
    }

#pragma unroll
    for (int rr = 0; rr < 2; rr++) {
        float2 o;
        o.x = cntx[rr] * (1.f / 16.f);
        o.y = cnty[rr] * (1.f / 16.f);
        *(float2*)(g_sf + (size_t)(n0 + wp * 2 + rr) * SU_DIM + i0) = o;
    }
}

// ---------------- K4: y = sf @ Weff^T + beff, LayerNorm, ReLU ----------------
// Block: 256 threads = 8 warps; 32 rows per block; warp owns 4 rows x full 512 cols.
__global__ __launch_bounds__(256) void k_final(const float* __restrict__ ln_g,
                                               const float* __restrict__ ln_b,
                                               float* __restrict__ out) {
    __shared__ float Wc[16][512];    // 32 KB   chunk of WeffT
    __shared__ float sfc[32][16];    // 2 KB

    const int tid = threadIdx.x;
    const int warp = tid >> 5;
    const int lane = tid & 31;
    const int n0 = blockIdx.x * 32;

    float acc[4][16];
#pragma unroll
    for (int r = 0; r < 4; r++)
#pragma unroll
        for (int kk = 0; kk < 16; kk++) acc[r][kk] = 0.f;

    for (int ic = 0; ic < 256; ic += 16) {
        __syncthreads();
#pragma unroll
        for (int p = 0; p < 8; p++) {
            int e4 = tid + p * 256;                 // 2048 float4 total
            int idx = e4 * 4;
            int ii = idx >> 9;
            int f = idx & 511;
            *(float4*)&Wc[ii][f] = *(const float4*)&g_WeffT[(size_t)(ic + ii) * 512 + f];
        }
#pragma unroll
        for (int p = 0; p < 2; p++) {
            int e = tid + p * 256;
            int row = e >> 4, ii = e & 15;
            sfc[row][ii] = g_sf[(size_t)(n0 + row) * 256 + ic + ii];
        }
        __syncthreads();

#pragma unroll
        for (int ii = 0; ii < 16; ii++) {
            float w[16];
#pragma unroll
            for (int kk = 0; kk < 16; kk++) w[kk] = Wc[ii][lane + 32 * kk];
            float a0 = sfc[warp * 4 + 0][ii];
            float a1 = sfc[warp * 4 + 1][ii];
            float a2 = sfc[warp * 4 + 2][ii];
            float a3 = sfc[warp * 4 + 3][ii];
#pragma unroll
            for (int kk = 0; kk < 16; kk++) {
                acc[0][kk] = fmaf(a0, w[kk], acc[0][kk]);
                acc[1][kk] = fmaf(a1, w[kk], acc[1][kk]);
                acc[2][kk] = fmaf(a2, w[kk], acc[2][kk]);
                acc[3][kk] = fmaf(a3, w[kk], acc[3][kk]);
            }
        }
    }

    float be[16], gg[16], bb[16];
#pragma unroll
    for (int kk = 0; kk < 16; kk++) {
        int f = lane + 32 * kk;
        be[kk] = g_beff[f];
        gg[kk] = ln_g[f];
        bb[kk] = ln_b[f];
    }

#pragma unroll
    for (int r = 0; r < 4; r++) {
        float y[16];
        float s = 0.f;
#pragma unroll
        for (int kk = 0; kk < 16; kk++) {
            y[kk] = acc[r][kk] + be[kk];
            s += y[kk];
        }
#pragma unroll
        for (int o = 16; o > 0; o >>= 1) s += __shfl_xor_sync(0xffffffffu, s, o);
        float mu = s * (1.f / 512.f);
        float sq = 0.f;
#pragma unroll
        for (int kk = 0; kk < 16; kk++) {
            float d = y[kk] - mu;
            sq = fmaf(d, d, sq);
        }
#pragma unroll
        for (int o = 16; o > 0; o >>= 1) sq += __shfl_xor_sync(0xffffffffu, sq, o);
        float rinv = rsqrtf(sq * (1.f / 512.f) + 1e-5f);

        int n = n0 + warp * 4 + r;
#pragma unroll
        for (int kk = 0; kk < 16; kk++) {
            float v = fmaf((y[kk] - mu) * rinv, gg[kk], bb[kk]);
            out[(size_t)n * 512 + lane + 32 * kk] = fmaxf(v, 0.f);
        }
    }
}

// ---------------- launch ----------------
extern "C" void kernel_launch(void* const* d_in, const int* in_sizes, int n_in,
                              void* d_out, int out_size) {
    const float* x    = (const float*)d_in[0];
    const float* W1   = (const float*)d_in[1];
    const float* b1   = (const float*)d_in[2];
    const float* W2   = (const float*)d_in[3];
    const float* b2   = (const float*)d_in[4];
    const float* Wf   = (const float*)d_in[5];
    const float* bf   = (const float*)d_in[6];
    const float* Wfu  = (const float*)d_in[7];
    const float* bfu  = (const float*)d_in[8];
    const float* ln_g = (const float*)d_in[9];
    const float* ln_b = (const float*)d_in[10];
    float* out = (float*)d_out;

    k_prep<<<1025, 256>>>(W2, Wfu, Wf, bf, bfu);
    k_gemm1<<<dim3(H1_DIM / K1_BN, N_ROWS / K1_BM), 256>>>(x, W1, b1);
    k_spike2<<<dim3(N_ROWS / 16, 4), 256>>>(b2);
    k_final<<<N_ROWS / 32, 256>>>(ln_g, ln_b, out);
}